// round 9
// baseline (speedup 1.0000x reference)
#include <cuda_runtime.h>
#include <math.h>

// GCNNet: 2x GCNConv(+self loops, sym norm) -> mean pool -> 4-layer MLP
// N=50000 nodes, E=800000 edges, 64 graphs, fp32 throughout.
//
//  - A(XW) == (AX)W : aggregate both layers at 64 channels.
//  - CSR build: histogram + device-wide scan (scan folded into apply).
//  - gemm1: 128 thr, 64x64 tile, 8x4 per-thread (halved LDS traffic vs 4x4).
//  - agg0 fuses layer-1 epilogue; fused2 = agg + GEMM2 + bias + relu +
//    MEAN-POOL accumulation (atomicAdd into g_pool) -> g_h2 eliminated.
//  - MLP: one block per graph; divides pooled sums by counts.

#define MAXN 50000
#define MAXE 800000
#define NG 64
#define NB_MAX 256

__device__ int   g_is64;
__device__ float g_dinv[MAXN];
__device__ int   g_cnt[MAXN];
__device__ int   g_rowstart[MAXN + 1];
__device__ int   g_cursor[MAXN];
__device__ int   g_csr[MAXE];
__device__ int   g_bsum[NB_MAX];
__device__ float g_hsA[MAXN * 64];
__device__ float g_hsB[MAXN * 64];
__device__ int   g_off[NG + 1];
__device__ float g_pool[NG * 128];

__device__ __forceinline__ int load_idx(const void* p, long long i) {
    return g_is64 ? (int)((const long long*)p)[i] : ((const int*)p)[i];
}

// ---------------------------------------------------------------------------
// zero histogram + pool accumulators + dtype detection.
__global__ void k_init(const int* ei_as_i32, int N) {
    int i = blockIdx.x * 256 + threadIdx.x;
    if (i < N) g_cnt[i] = 0;
    if (i < NG * 128) g_pool[i] = 0.f;
    if (blockIdx.x == 0 && threadIdx.x < 32) {
        unsigned m = __ballot_sync(0xffffffffu, ei_as_i32[2 * threadIdx.x + 1] != 0);
        if (threadIdx.x == 0) g_is64 = (m == 0u) ? 1 : 0;
    }
}

__global__ void k_hist(const void* ei, int E) {
    int e = blockIdx.x * blockDim.x + threadIdx.x;
    if (e >= E) return;
    int d = load_idx(ei, (long long)E + e);
    atomicAdd(&g_cnt[d], 1);
}

__global__ void k_blocksum(int N) {
    int i = blockIdx.x * 256 + threadIdx.x;
    int v = (i < N) ? g_cnt[i] : 0;
#pragma unroll
    for (int o = 16; o; o >>= 1) v += __shfl_down_sync(0xffffffffu, v, o);
    __shared__ int ws[8];
    if ((threadIdx.x & 31) == 0) ws[threadIdx.x >> 5] = v;
    __syncthreads();
    if (threadIdx.x == 0) {
        int s = 0;
#pragma unroll
        for (int j = 0; j < 8; j++) s += ws[j];
        g_bsum[blockIdx.x] = s;
    }
}

__global__ __launch_bounds__(256) void k_apply(const void* bt, int NB, int E, int N) {
    __shared__ int sb[256];
    __shared__ int wt[8];
    __shared__ int wo[8];
    int t = threadIdx.x;

    sb[t] = (t < NB) ? g_bsum[t] : 0;
    __syncthreads();
    for (int o = 1; o < 256; o <<= 1) {
        int val = sb[t];
        int add = (t >= o) ? sb[t - o] : 0;
        __syncthreads();
        sb[t] = val + add;
        __syncthreads();
    }
    int blockoff = (blockIdx.x == 0) ? 0 : sb[blockIdx.x - 1];

    int i = blockIdx.x * 256 + t;
    int c = (i < N) ? g_cnt[i] : 0;
    int lane = t & 31, w = t >> 5;
    int x = c;
#pragma unroll
    for (int o = 1; o < 32; o <<= 1) {
        int y = __shfl_up_sync(0xffffffffu, x, o);
        if (lane >= o) x += y;
    }
    if (lane == 31) wt[w] = x;
    __syncthreads();
    if (t < 8) {
        int s = 0;
        for (int j = 0; j < t; j++) s += wt[j];
        wo[t] = s;
    }
    __syncthreads();
    if (i < N) {
        int excl = x - c + wo[w] + blockoff;
        g_rowstart[i] = excl;
        g_cursor[i]   = excl;
        g_dinv[i]     = rsqrtf((float)(c + 1));  // +1 self loop

        int b  = load_idx(bt, i);
        int bp = (i == 0) ? -1 : load_idx(bt, i - 1);
        for (int g = bp + 1; g <= b; g++) g_off[g] = i;
        if (i == N - 1) {
            for (int g = b + 1; g <= NG; g++) g_off[g] = N;
        }
    }
    if (i == 0) g_rowstart[N] = E;
}

__global__ void k_fill(const void* ei, int E) {
    int e = blockIdx.x * blockDim.x + threadIdx.x;
    if (e >= E) return;
    int d = load_idx(ei, (long long)E + e);
    int s = load_idx(ei, e);
    int pos = atomicAdd(&g_cursor[d], 1);
    g_csr[pos] = s;
}

// ---------------------------------------------------------------------------
// GEMM1: hsA[r][c] = (x[r] @ W1)[c]   (UNSCALED; dinv applied in agg0)
// 128 threads, 64 rows x 64 cols per block, 8x4 per thread, K halved (2 stages).
__global__ __launch_bounds__(128) void k_gemm1(const float* __restrict__ x,
                                               const float* __restrict__ W1, int N) {
    __shared__ float xs[64 * 64];   // 16KB, per K-half
    __shared__ float ws[64 * 64];   // 16KB, per K-half
    int t = threadIdx.x;
    int row0 = blockIdx.x * 64;
    int rg = t >> 4, cg = t & 15;   // rows rg*8..+7, cols cg*4..+3

    float a[8][4] = {};
    const float4* W14 = (const float4*)W1;
    const float4* x4  = (const float4*)x;
    float4* ws4 = (float4*)ws;
    float4* xs4 = (float4*)xs;

    for (int kh = 0; kh < 2; kh++) {
        __syncthreads();
        for (int i = t; i < 1024; i += 128) {
            int k = i >> 4, c4 = i & 15;
            ws4[i] = W14[(size_t)(kh * 64 + k) * 16 + c4];
        }
        for (int i = t; i < 1024; i += 128) {
            int r = i >> 4, kk = i & 15;
            int gr = row0 + r;
            xs4[r * 16 + kk] = (gr < N) ? x4[(size_t)gr * 32 + kh * 16 + kk]
                                        : make_float4(0.f, 0.f, 0.f, 0.f);
        }
        __syncthreads();
#pragma unroll
        for (int k = 0; k < 64; k += 4) {
            float4 xv[8];
#pragma unroll
            for (int i = 0; i < 8; i++)
                xv[i] = *(const float4*)&xs[(rg * 8 + i) * 64 + k];
#pragma unroll
            for (int kk = 0; kk < 4; kk++) {
                float4 w = *(const float4*)&ws[(k + kk) * 64 + cg * 4];
#pragma unroll
                for (int i = 0; i < 8; i++) {
                    float xvv = ((const float*)&xv[i])[kk];
                    a[i][0] += xvv * w.x; a[i][1] += xvv * w.y;
                    a[i][2] += xvv * w.z; a[i][3] += xvv * w.w;
                }
            }
        }
    }
#pragma unroll
    for (int i = 0; i < 8; i++) {
        int gr = row0 + rg * 8 + i;
        if (gr < N) {
            *(float4*)&g_hsA[(size_t)gr * 64 + cg * 4] =
                make_float4(a[i][0], a[i][1], a[i][2], a[i][3]);
        }
    }
}

// ---------------------------------------------------------------------------
// agg0: hsB = relu( (Σ hsA[src]*dinv[src] + hsA[i]*dinv[i]) * dinv[i] + b1 ) * dinv[i]
__global__ __launch_bounds__(256) void k_agg0(const float* __restrict__ b1, int N) {
    const float2* hs = (const float2*)g_hsA;
    int warp = (blockIdx.x * blockDim.x + threadIdx.x) >> 5;
    int lane = threadIdx.x & 31;
    if (warp >= N) return;

    int s = g_rowstart[warp];
    int e = g_rowstart[warp + 1];
    float d = g_dinv[warp];
    float2 acc = hs[(size_t)warp * 32 + lane];  // self loop
    acc.x *= d; acc.y *= d;
    int j = s;
    for (; j + 3 < e; j += 4) {
        int s0 = g_csr[j], s1 = g_csr[j + 1], s2 = g_csr[j + 2], s3 = g_csr[j + 3];
        float d0 = g_dinv[s0], d1 = g_dinv[s1], d2 = g_dinv[s2], d3 = g_dinv[s3];
        float2 v0 = hs[(size_t)s0 * 32 + lane];
        float2 v1 = hs[(size_t)s1 * 32 + lane];
        float2 v2 = hs[(size_t)s2 * 32 + lane];
        float2 v3 = hs[(size_t)s3 * 32 + lane];
        acc.x += v0.x * d0 + v1.x * d1 + v2.x * d2 + v3.x * d3;
        acc.y += v0.y * d0 + v1.y * d1 + v2.y * d2 + v3.y * d3;
    }
    for (; j < e; j++) {
        int s0 = g_csr[j];
        float d0 = g_dinv[s0];
        float2 v0 = hs[(size_t)s0 * 32 + lane];
        acc.x += v0.x * d0;
        acc.y += v0.y * d0;
    }
    float2 bb = __ldg(&((const float2*)b1)[lane]);
    float2 o;
    o.x = fmaxf(acc.x * d + bb.x, 0.f) * d;
    o.y = fmaxf(acc.y * d + bb.y, 0.f) * d;
    ((float2*)g_hsB)[(size_t)warp * 32 + lane] = o;
}

// ---------------------------------------------------------------------------
// Fused layer-2 + POOL: agg over hsB -> shared -> GEMM vs W2[64,128]
// (+b2, relu) -> atomicAdd per-graph channel sums into g_pool.
// 256 threads, 64 nodes/block, full W2 resident (48KB smem total).
__global__ __launch_bounds__(256) void k_fused2(const float* __restrict__ W2,
                                                const float* __restrict__ b2,
                                                const void* __restrict__ bt, int N) {
    __shared__ float xs[64 * 64];    // 16KB
    __shared__ float ws[64 * 128];   // 32KB
    int t = threadIdx.x;
    int warp = t >> 5, lane = t & 31;
    int row0 = blockIdx.x * 64;

    const float4* W24 = (const float4*)W2;
    for (int i = t; i < 2048; i += 256) ((float4*)ws)[i] = W24[i];

    const float2* hs = (const float2*)g_hsB;
    for (int p = 0; p < 8; p++) {
        int r = p * 8 + warp;
        int node = row0 + r;
        float2 acc = make_float2(0.f, 0.f);
        if (node < N) {
            int s = g_rowstart[node], e = g_rowstart[node + 1];
            acc = hs[(size_t)node * 32 + lane];
            int j = s;
            for (; j + 3 < e; j += 4) {
                int s0 = g_csr[j], s1 = g_csr[j + 1], s2 = g_csr[j + 2], s3 = g_csr[j + 3];
                float2 v0 = hs[(size_t)s0 * 32 + lane];
                float2 v1 = hs[(size_t)s1 * 32 + lane];
                float2 v2 = hs[(size_t)s2 * 32 + lane];
                float2 v3 = hs[(size_t)s3 * 32 + lane];
                acc.x += (v0.x + v1.x) + (v2.x + v3.x);
                acc.y += (v0.y + v1.y) + (v2.y + v3.y);
            }
            for (; j < e; j++) {
                int s0 = g_csr[j];
                float2 v0 = hs[(size_t)s0 * 32 + lane];
                acc.x += v0.x;
                acc.y += v0.y;
            }
            float d = g_dinv[node];
            acc.x *= d; acc.y *= d;
        }
        ((float2*)xs)[r * 32 + lane] = acc;
    }
    __syncthreads();

    // GEMM: thread tile 4 rows x 8 cols over [64 x 128]
    int rg = t >> 4, cg = t & 15;   // rows 4rg..+3, cols cg*8..+7
    float a[4][8] = {};
#pragma unroll
    for (int k = 0; k < 64; k += 4) {
        float4 xv[4];
#pragma unroll
        for (int i = 0; i < 4; i++)
            xv[i] = *(const float4*)&xs[(4 * rg + i) * 64 + k];
#pragma unroll
        for (int kk = 0; kk < 4; kk++) {
            float4 w0 = *(const float4*)&ws[(k + kk) * 128 + cg * 8];
            float4 w1 = *(const float4*)&ws[(k + kk) * 128 + cg * 8 + 4];
#pragma unroll
            for (int i = 0; i < 4; i++) {
                float xvv = ((const float*)&xv[i])[kk];
                a[i][0] += xvv * w0.x; a[i][1] += xvv * w0.y;
                a[i][2] += xvv * w0.z; a[i][3] += xvv * w0.w;
                a[i][4] += xvv * w1.x; a[i][5] += xvv * w1.y;
                a[i][6] += xvv * w1.z; a[i][7] += xvv * w1.w;
            }
        }
    }

    // epilogue: bias + relu, then per-graph pooled atomics
    float4 bb0 = __ldg((const float4*)&b2[cg * 8]);
    float4 bb1 = __ldg((const float4*)&b2[cg * 8 + 4]);
    float bias[8] = {bb0.x, bb0.y, bb0.z, bb0.w, bb1.x, bb1.y, bb1.z, bb1.w};

    int bidx[4];
#pragma unroll
    for (int i = 0; i < 4; i++) {
        int gr = row0 + 4 * rg + i;
        bidx[i] = (gr < N) ? load_idx(bt, gr) : -1;
#pragma unroll
        for (int j = 0; j < 8; j++) a[i][j] = fmaxf(a[i][j] + bias[j], 0.f);
    }

    if (bidx[0] >= 0 && bidx[0] == bidx[1] && bidx[0] == bidx[2] && bidx[0] == bidx[3]) {
        float* dst = &g_pool[bidx[0] * 128 + cg * 8];
#pragma unroll
        for (int j = 0; j < 8; j++)
            atomicAdd(&dst[j], (a[0][j] + a[1][j]) + (a[2][j] + a[3][j]));
    } else {
#pragma unroll
        for (int i = 0; i < 4; i++) {
            if (bidx[i] >= 0) {
                float* dst = &g_pool[bidx[i] * 128 + cg * 8];
#pragma unroll
                for (int j = 0; j < 8; j++) atomicAdd(&dst[j], a[i][j]);
            }
        }
    }
}

// ---------------------------------------------------------------------------
// MLP: one block per graph, 64 threads. Layers: 128->64->64->64->1.
// Divides pooled sums by graph node count on load.
__global__ __launch_bounds__(64) void k_mlp(const float* __restrict__ M1, const float* __restrict__ c1,
                                            const float* __restrict__ M2, const float* __restrict__ c2,
                                            const float* __restrict__ M3, const float* __restrict__ c3,
                                            const float* __restrict__ M4, const float* __restrict__ c4,
                                            float* __restrict__ out) {
    int g = blockIdx.x;
    int t = threadIdx.x;
    __shared__ float A[128];
    __shared__ float B[64];
    __shared__ float C[64];
    __shared__ float red[64];

    float inv = 1.f / fmaxf((float)(g_off[g + 1] - g_off[g]), 1.f);
    A[t]      = g_pool[g * 128 + t] * inv;
    A[t + 64] = g_pool[g * 128 + 64 + t] * inv;
    __syncthreads();

    {
        float acc = 0.f;
#pragma unroll 4
        for (int k = 0; k < 128; k++) acc += A[k] * __ldg(&M1[k * 64 + t]);
        float v = acc + __ldg(&c1[t]);
        B[t] = (v > 0.f) ? v : 0.2f * v;
    }
    __syncthreads();

    {
        float acc = 0.f;
#pragma unroll 4
        for (int k = 0; k < 64; k++) acc += B[k] * __ldg(&M2[k * 64 + t]);
        float v = acc + __ldg(&c2[t]);
        C[t] = (v > 0.f) ? v : 0.1f * v;
    }
    __syncthreads();

    {
        float acc = 0.f;
#pragma unroll 4
        for (int k = 0; k < 64; k++) acc += C[k] * __ldg(&M3[k * 64 + t]);
        float v = acc + __ldg(&c3[t]);
        red[t] = (v > 0.f) ? v : 0.1f * v;
    }
    __syncthreads();

    float p = red[t] * __ldg(&M4[t]);
    __syncthreads();
    red[t] = p;
    __syncthreads();
    if (t < 32) {
        float v = red[t] + red[t + 32];
#pragma unroll
        for (int o = 16; o; o >>= 1) v += __shfl_down_sync(0xffffffffu, v, o);
        if (t == 0) out[g] = fmaxf(v + __ldg(&c4[0]), 0.f);
    }
}

// ---------------------------------------------------------------------------
extern "C" void kernel_launch(void* const* d_in, const int* in_sizes, int n_in,
                              void* d_out, int out_size) {
    const float* x  = (const float*)d_in[0];
    const void*  ei = d_in[1];
    const void*  bt = d_in[2];
    const float* W1 = (const float*)d_in[3];
    const float* b1 = (const float*)d_in[4];
    const float* W2 = (const float*)d_in[5];
    const float* b2 = (const float*)d_in[6];
    const float* M1 = (const float*)d_in[7];
    const float* c1 = (const float*)d_in[8];
    const float* M2 = (const float*)d_in[9];
    const float* c2 = (const float*)d_in[10];
    const float* M3 = (const float*)d_in[11];
    const float* c3 = (const float*)d_in[12];
    const float* M4 = (const float*)d_in[13];
    const float* c4 = (const float*)d_in[14];
    float* out = (float*)d_out;

    int E = in_sizes[1] / 2;   // 800000
    int N = in_sizes[2];       // 50000
    int NB = (N + 255) / 256;  // 196

    k_init<<<NB, 256>>>((const int*)ei, N);
    k_hist<<<(E + 255) / 256, 256>>>(ei, E);
    k_blocksum<<<NB, 256>>>(N);
    k_gemm1<<<(N + 63) / 64, 128>>>(x, W1, N);   // 4th: profiled by ncu
    k_apply<<<NB, 256>>>(bt, NB, E, N);
    k_fill<<<(E + 255) / 256, 256>>>(ei, E);
    k_agg0<<<(N + 7) / 8, 256>>>(b1, N);
    k_fused2<<<(N + 63) / 64, 256>>>(W2, b2, bt, N);
    k_mlp<<<NG, 64>>>(M1, c1, M2, c2, M3, c3, M4, c4, out);
}

// round 10
// speedup vs baseline: 1.0838x; 1.0838x over previous
#include <cuda_runtime.h>
#include <math.h>

// GCNNet: 2x GCNConv(+self loops, sym norm) -> mean pool -> 4-layer MLP
// N=50000 nodes, E=800000 edges, 64 graphs, fp32 throughout.
//
//  - A(XW) == (AX)W : aggregate both layers at 64 channels.
//  - CSR build: histogram + device-wide scan (scan folded into apply).
//  - gemm1 (no deps: dinv applied in agg0) runs on a SIDE STREAM overlapped
//    with the whole CSR build; joined before agg0.
//  - agg0 fuses layer-1 epilogue; fused2 = agg + GEMM2 + bias + relu -> h2.
//    (pooled-atomic epilogue REVERTED: 780-way LTS contention cost +10us)
//  - pool + MLP merged: one block per graph reduces h2 then runs the MLP.

#define MAXN 50000
#define MAXE 800000
#define NG 64
#define NB_MAX 256

__device__ int   g_is64;
__device__ float g_dinv[MAXN];
__device__ int   g_cnt[MAXN];
__device__ int   g_rowstart[MAXN + 1];
__device__ int   g_cursor[MAXN];
__device__ int   g_csr[MAXE];
__device__ int   g_bsum[NB_MAX];
__device__ float g_hsA[MAXN * 64];
__device__ float g_hsB[MAXN * 64];
__device__ float g_h2[(size_t)MAXN * 128];
__device__ int   g_off[NG + 1];

__device__ __forceinline__ int load_idx(const void* p, long long i) {
    return g_is64 ? (int)((const long long*)p)[i] : ((const int*)p)[i];
}

// Side stream + events (host objects, created once at load; no device allocs).
namespace {
struct Aux {
    cudaStream_t s;
    cudaEvent_t fork, join;
    Aux() {
        cudaStreamCreateWithFlags(&s, cudaStreamNonBlocking);
        cudaEventCreateWithFlags(&fork, cudaEventDisableTiming);
        cudaEventCreateWithFlags(&join, cudaEventDisableTiming);
    }
};
Aux g_aux;
}

// ---------------------------------------------------------------------------
// zero histogram + dtype detection.
__global__ void k_init(const int* ei_as_i32, int N) {
    int i = blockIdx.x * 256 + threadIdx.x;
    if (i < N) g_cnt[i] = 0;
    if (blockIdx.x == 0 && threadIdx.x < 32) {
        unsigned m = __ballot_sync(0xffffffffu, ei_as_i32[2 * threadIdx.x + 1] != 0);
        if (threadIdx.x == 0) g_is64 = (m == 0u) ? 1 : 0;
    }
}

__global__ void k_hist(const void* ei, int E) {
    int e = blockIdx.x * blockDim.x + threadIdx.x;
    if (e >= E) return;
    int d = load_idx(ei, (long long)E + e);
    atomicAdd(&g_cnt[d], 1);
}

__global__ void k_blocksum(int N) {
    int i = blockIdx.x * 256 + threadIdx.x;
    int v = (i < N) ? g_cnt[i] : 0;
#pragma unroll
    for (int o = 16; o; o >>= 1) v += __shfl_down_sync(0xffffffffu, v, o);
    __shared__ int ws[8];
    if ((threadIdx.x & 31) == 0) ws[threadIdx.x >> 5] = v;
    __syncthreads();
    if (threadIdx.x == 0) {
        int s = 0;
#pragma unroll
        for (int j = 0; j < 8; j++) s += ws[j];
        g_bsum[blockIdx.x] = s;
    }
}

__global__ __launch_bounds__(256) void k_apply(const void* bt, int NB, int E, int N) {
    __shared__ int sb[256];
    __shared__ int wt[8];
    __shared__ int wo[8];
    int t = threadIdx.x;

    sb[t] = (t < NB) ? g_bsum[t] : 0;
    __syncthreads();
    for (int o = 1; o < 256; o <<= 1) {
        int val = sb[t];
        int add = (t >= o) ? sb[t - o] : 0;
        __syncthreads();
        sb[t] = val + add;
        __syncthreads();
    }
    int blockoff = (blockIdx.x == 0) ? 0 : sb[blockIdx.x - 1];

    int i = blockIdx.x * 256 + t;
    int c = (i < N) ? g_cnt[i] : 0;
    int lane = t & 31, w = t >> 5;
    int x = c;
#pragma unroll
    for (int o = 1; o < 32; o <<= 1) {
        int y = __shfl_up_sync(0xffffffffu, x, o);
        if (lane >= o) x += y;
    }
    if (lane == 31) wt[w] = x;
    __syncthreads();
    if (t < 8) {
        int s = 0;
        for (int j = 0; j < t; j++) s += wt[j];
        wo[t] = s;
    }
    __syncthreads();
    if (i < N) {
        int excl = x - c + wo[w] + blockoff;
        g_rowstart[i] = excl;
        g_cursor[i]   = excl;
        g_dinv[i]     = rsqrtf((float)(c + 1));  // +1 self loop

        int b  = load_idx(bt, i);
        int bp = (i == 0) ? -1 : load_idx(bt, i - 1);
        for (int g = bp + 1; g <= b; g++) g_off[g] = i;
        if (i == N - 1) {
            for (int g = b + 1; g <= NG; g++) g_off[g] = N;
        }
    }
    if (i == 0) g_rowstart[N] = E;
}

__global__ void k_fill(const void* ei, int E) {
    int e = blockIdx.x * blockDim.x + threadIdx.x;
    if (e >= E) return;
    int d = load_idx(ei, (long long)E + e);
    int s = load_idx(ei, e);
    int pos = atomicAdd(&g_cursor[d], 1);
    g_csr[pos] = s;
}

// ---------------------------------------------------------------------------
// GEMM1: hsA[r][c] = (x[r] @ W1)[c]   (UNSCALED; dinv applied in agg0)
// 128 threads, 64x64 tile, 8x4 per thread, K halved (2 stages). FMA-floor-bound.
__global__ __launch_bounds__(128) void k_gemm1(const float* __restrict__ x,
                                               const float* __restrict__ W1, int N) {
    __shared__ float xs[64 * 64];
    __shared__ float ws[64 * 64];
    int t = threadIdx.x;
    int row0 = blockIdx.x * 64;
    int rg = t >> 4, cg = t & 15;

    float a[8][4] = {};
    const float4* W14 = (const float4*)W1;
    const float4* x4  = (const float4*)x;
    float4* ws4 = (float4*)ws;
    float4* xs4 = (float4*)xs;

    for (int kh = 0; kh < 2; kh++) {
        __syncthreads();
        for (int i = t; i < 1024; i += 128) {
            int k = i >> 4, c4 = i & 15;
            ws4[i] = W14[(size_t)(kh * 64 + k) * 16 + c4];
        }
        for (int i = t; i < 1024; i += 128) {
            int r = i >> 4, kk = i & 15;
            int gr = row0 + r;
            xs4[r * 16 + kk] = (gr < N) ? x4[(size_t)gr * 32 + kh * 16 + kk]
                                        : make_float4(0.f, 0.f, 0.f, 0.f);
        }
        __syncthreads();
#pragma unroll
        for (int k = 0; k < 64; k += 4) {
            float4 xv[8];
#pragma unroll
            for (int i = 0; i < 8; i++)
                xv[i] = *(const float4*)&xs[(rg * 8 + i) * 64 + k];
#pragma unroll
            for (int kk = 0; kk < 4; kk++) {
                float4 w = *(const float4*)&ws[(k + kk) * 64 + cg * 4];
#pragma unroll
                for (int i = 0; i < 8; i++) {
                    float xvv = ((const float*)&xv[i])[kk];
                    a[i][0] += xvv * w.x; a[i][1] += xvv * w.y;
                    a[i][2] += xvv * w.z; a[i][3] += xvv * w.w;
                }
            }
        }
    }
#pragma unroll
    for (int i = 0; i < 8; i++) {
        int gr = row0 + rg * 8 + i;
        if (gr < N) {
            *(float4*)&g_hsA[(size_t)gr * 64 + cg * 4] =
                make_float4(a[i][0], a[i][1], a[i][2], a[i][3]);
        }
    }
}

// ---------------------------------------------------------------------------
// agg0: hsB = relu( (Σ hsA[src]*dinv[src] + hsA[i]*dinv[i]) * dinv[i] + b1 ) * dinv[i]
__global__ __launch_bounds__(256) void k_agg0(const float* __restrict__ b1, int N) {
    const float2* hs = (const float2*)g_hsA;
    int warp = (blockIdx.x * blockDim.x + threadIdx.x) >> 5;
    int lane = threadIdx.x & 31;
    if (warp >= N) return;

    int s = g_rowstart[warp];
    int e = g_rowstart[warp + 1];
    float d = g_dinv[warp];
    float2 acc = hs[(size_t)warp * 32 + lane];  // self loop
    acc.x *= d; acc.y *= d;
    int j = s;
    for (; j + 3 < e; j += 4) {
        int s0 = g_csr[j], s1 = g_csr[j + 1], s2 = g_csr[j + 2], s3 = g_csr[j + 3];
        float d0 = g_dinv[s0], d1 = g_dinv[s1], d2 = g_dinv[s2], d3 = g_dinv[s3];
        float2 v0 = hs[(size_t)s0 * 32 + lane];
        float2 v1 = hs[(size_t)s1 * 32 + lane];
        float2 v2 = hs[(size_t)s2 * 32 + lane];
        float2 v3 = hs[(size_t)s3 * 32 + lane];
        acc.x += v0.x * d0 + v1.x * d1 + v2.x * d2 + v3.x * d3;
        acc.y += v0.y * d0 + v1.y * d1 + v2.y * d2 + v3.y * d3;
    }
    for (; j < e; j++) {
        int s0 = g_csr[j];
        float d0 = g_dinv[s0];
        float2 v0 = hs[(size_t)s0 * 32 + lane];
        acc.x += v0.x * d0;
        acc.y += v0.y * d0;
    }
    float2 bb = __ldg(&((const float2*)b1)[lane]);
    float2 o;
    o.x = fmaxf(acc.x * d + bb.x, 0.f) * d;
    o.y = fmaxf(acc.y * d + bb.y, 0.f) * d;
    ((float2*)g_hsB)[(size_t)warp * 32 + lane] = o;
}

// ---------------------------------------------------------------------------
// Fused layer-2: agg over hsB -> shared -> GEMM vs W2[64,128] (+b2, relu) -> h2
// 256 threads, 64 nodes/block, full W2 resident (48KB smem total).
__global__ __launch_bounds__(256) void k_fused2(const float* __restrict__ W2,
                                                const float* __restrict__ b2, int N) {
    __shared__ float xs[64 * 64];    // 16KB
    __shared__ float ws[64 * 128];   // 32KB
    int t = threadIdx.x;
    int warp = t >> 5, lane = t & 31;
    int row0 = blockIdx.x * 64;

    const float4* W24 = (const float4*)W2;
    for (int i = t; i < 2048; i += 256) ((float4*)ws)[i] = W24[i];

    const float2* hs = (const float2*)g_hsB;
    for (int p = 0; p < 8; p++) {
        int r = p * 8 + warp;
        int node = row0 + r;
        float2 acc = make_float2(0.f, 0.f);
        if (node < N) {
            int s = g_rowstart[node], e = g_rowstart[node + 1];
            acc = hs[(size_t)node * 32 + lane];
            int j = s;
            for (; j + 3 < e; j += 4) {
                int s0 = g_csr[j], s1 = g_csr[j + 1], s2 = g_csr[j + 2], s3 = g_csr[j + 3];
                float2 v0 = hs[(size_t)s0 * 32 + lane];
                float2 v1 = hs[(size_t)s1 * 32 + lane];
                float2 v2 = hs[(size_t)s2 * 32 + lane];
                float2 v3 = hs[(size_t)s3 * 32 + lane];
                acc.x += (v0.x + v1.x) + (v2.x + v3.x);
                acc.y += (v0.y + v1.y) + (v2.y + v3.y);
            }
            for (; j < e; j++) {
                int s0 = g_csr[j];
                float2 v0 = hs[(size_t)s0 * 32 + lane];
                acc.x += v0.x;
                acc.y += v0.y;
            }
            float d = g_dinv[node];
            acc.x *= d; acc.y *= d;
        }
        ((float2*)xs)[r * 32 + lane] = acc;
    }
    __syncthreads();

    // GEMM: thread tile 4 rows x 8 cols over [64 x 128]
    int rg = t >> 4, cg = t & 15;
    float a[4][8] = {};
#pragma unroll
    for (int k = 0; k < 64; k += 4) {
        float4 xv[4];
#pragma unroll
        for (int i = 0; i < 4; i++)
            xv[i] = *(const float4*)&xs[(4 * rg + i) * 64 + k];
#pragma unroll
        for (int kk = 0; kk < 4; kk++) {
            float4 w0 = *(const float4*)&ws[(k + kk) * 128 + cg * 8];
            float4 w1 = *(const float4*)&ws[(k + kk) * 128 + cg * 8 + 4];
#pragma unroll
            for (int i = 0; i < 4; i++) {
                float xvv = ((const float*)&xv[i])[kk];
                a[i][0] += xvv * w0.x; a[i][1] += xvv * w0.y;
                a[i][2] += xvv * w0.z; a[i][3] += xvv * w0.w;
                a[i][4] += xvv * w1.x; a[i][5] += xvv * w1.y;
                a[i][6] += xvv * w1.z; a[i][7] += xvv * w1.w;
            }
        }
    }

    float4 bb0 = __ldg((const float4*)&b2[cg * 8]);
    float4 bb1 = __ldg((const float4*)&b2[cg * 8 + 4]);
#pragma unroll
    for (int i = 0; i < 4; i++) {
        int gr = row0 + 4 * rg + i;
        if (gr < N) {
            *(float4*)&g_h2[(size_t)gr * 128 + cg * 8] =
                make_float4(fmaxf(a[i][0] + bb0.x, 0.f), fmaxf(a[i][1] + bb0.y, 0.f),
                            fmaxf(a[i][2] + bb0.z, 0.f), fmaxf(a[i][3] + bb0.w, 0.f));
            *(float4*)&g_h2[(size_t)gr * 128 + cg * 8 + 4] =
                make_float4(fmaxf(a[i][4] + bb1.x, 0.f), fmaxf(a[i][5] + bb1.y, 0.f),
                            fmaxf(a[i][6] + bb1.z, 0.f), fmaxf(a[i][7] + bb1.w, 0.f));
        }
    }
}

// ---------------------------------------------------------------------------
// Pool + MLP merged: one block per graph. 1024 threads reduce h2 -> mean,
// then threads 0..63 run the 4-layer MLP.
__global__ __launch_bounds__(1024) void k_poolmlp(
        const float* __restrict__ M1, const float* __restrict__ c1,
        const float* __restrict__ M2, const float* __restrict__ c2,
        const float* __restrict__ M3, const float* __restrict__ c3,
        const float* __restrict__ M4, const float* __restrict__ c4,
        float* __restrict__ out) {
    int g = blockIdx.x;
    int t = threadIdx.x;
    int c = t & 127;
    int grp = t >> 7;
    int s = g_off[g], e = g_off[g + 1];

    __shared__ float sh[1024];
    __shared__ float A[128];
    __shared__ float B[64];
    __shared__ float C[64];
    __shared__ float red[64];

    float sum = 0.f;
    for (int r = s + grp; r < e; r += 8) sum += g_h2[(size_t)r * 128 + c];
    sh[t] = sum;
    __syncthreads();
    if (grp == 0) {
        float tot = sh[c] + sh[c + 128] + sh[c + 256] + sh[c + 384] +
                    sh[c + 512] + sh[c + 640] + sh[c + 768] + sh[c + 896];
        A[c] = tot / fmaxf((float)(e - s), 1.f);
    }
    __syncthreads();

    if (t < 64) {
        // L1: B = leaky0.2(A @ M1[128,64] + c1)
        float acc = 0.f;
#pragma unroll 4
        for (int k = 0; k < 128; k++) acc += A[k] * __ldg(&M1[k * 64 + t]);
        float v = acc + __ldg(&c1[t]);
        B[t] = (v > 0.f) ? v : 0.2f * v;
    }
    __syncthreads();
    if (t < 64) {
        float acc = 0.f;
#pragma unroll 4
        for (int k = 0; k < 64; k++) acc += B[k] * __ldg(&M2[k * 64 + t]);
        float v = acc + __ldg(&c2[t]);
        C[t] = (v > 0.f) ? v : 0.1f * v;
    }
    __syncthreads();
    if (t < 64) {
        float acc = 0.f;
#pragma unroll 4
        for (int k = 0; k < 64; k++) acc += C[k] * __ldg(&M3[k * 64 + t]);
        float v = acc + __ldg(&c3[t]);
        red[t] = (v > 0.f) ? v : 0.1f * v;
    }
    __syncthreads();
    if (t < 64) {
        float p = red[t] * __ldg(&M4[t]);
        red[t] = p;
    }
    __syncthreads();
    if (t < 32) {
        float v = red[t] + red[t + 32];
#pragma unroll
        for (int o = 16; o; o >>= 1) v += __shfl_down_sync(0xffffffffu, v, o);
        if (t == 0) out[g] = fmaxf(v + __ldg(&c4[0]), 0.f);
    }
}

// ---------------------------------------------------------------------------
extern "C" void kernel_launch(void* const* d_in, const int* in_sizes, int n_in,
                              void* d_out, int out_size) {
    const float* x  = (const float*)d_in[0];
    const void*  ei = d_in[1];
    const void*  bt = d_in[2];
    const float* W1 = (const float*)d_in[3];
    const float* b1 = (const float*)d_in[4];
    const float* W2 = (const float*)d_in[5];
    const float* b2 = (const float*)d_in[6];
    const float* M1 = (const float*)d_in[7];
    const float* c1 = (const float*)d_in[8];
    const float* M2 = (const float*)d_in[9];
    const float* c2 = (const float*)d_in[10];
    const float* M3 = (const float*)d_in[11];
    const float* c3 = (const float*)d_in[12];
    const float* M4 = (const float*)d_in[13];
    const float* c4 = (const float*)d_in[14];
    float* out = (float*)d_out;

    int E = in_sizes[1] / 2;   // 800000
    int N = in_sizes[2];       // 50000
    int NB = (N + 255) / 256;  // 196

    // fork: gemm1 has no dependencies -> side stream, overlaps CSR build
    cudaEventRecord(g_aux.fork, 0);
    cudaStreamWaitEvent(g_aux.s, g_aux.fork, 0);
    k_gemm1<<<(N + 63) / 64, 128, 0, g_aux.s>>>(x, W1, N);
    cudaEventRecord(g_aux.join, g_aux.s);

    // CSR build chain on the main stream
    k_init<<<NB, 256>>>((const int*)ei, N);
    k_hist<<<(E + 255) / 256, 256>>>(ei, E);
    k_blocksum<<<NB, 256>>>(N);
    k_apply<<<NB, 256>>>(bt, NB, E, N);
    k_fill<<<(E + 255) / 256, 256>>>(ei, E);

    // join: agg0 needs both gemm1 (hsA) and the CSR
    cudaStreamWaitEvent(0, g_aux.join, 0);
    k_agg0<<<(N + 7) / 8, 256>>>(b1, N);
    k_fused2<<<(N + 63) / 64, 256>>>(W2, b2, N);
    k_poolmlp<<<NG, 1024>>>(M1, c1, M2, c2, M3, c3, M4, c4, out);
}